// round 10
// baseline (speedup 1.0000x reference)
#include <cuda_runtime.h>
#include <cstdint>

#define N_NODES 50000
#define NPAD    50048   // 64*782
#define NE      800000
#define HD      64
#define TSTEPS  4
#define RSTRIDE 68      // muT row stride in floats (17 16B-slots, odd)
#define WSTRIDE 68      // Ws row stride in floats

// ---------- device scratch ----------
__device__ float g_deg[N_NODES];
__device__ float g_sw[N_NODES];
__device__ float g_c3[TSTEPS * HD];
__device__ float g_S[HD];
__device__ float g_WT[5][HD][HD];      // [0..3]=W2[t]^T, [4]=W7^T
__device__ float g_muT[HD][NPAD];      // transposed mu

// ---------- f32x2 helpers ----------
__device__ __forceinline__ void ffma2(uint64_t& acc, uint64_t a, uint64_t b) {
    asm("fma.rn.f32x2 %0, %1, %2, %0;" : "+l"(acc) : "l"(a), "l"(b));
}
__device__ __forceinline__ uint64_t splat2(float v) {
    uint64_t r;
    asm("mov.b64 %0, {%1, %1};" : "=l"(r) : "f"(v));
    return r;
}
__device__ __forceinline__ float2 unpack2(uint64_t v) {
    float lo, hi;
    asm("mov.b64 {%0, %1}, %2;" : "=f"(lo), "=f"(hi) : "l"(v));
    return make_float2(lo, hi);
}
__device__ __forceinline__ uint32_t sptr(const void* p) {
    uint32_t r;
    asm("{.reg .u64 t; cvta.to.shared.u64 t, %1; cvt.u32.u64 %0, t;}"
        : "=r"(r) : "l"(p));
    return r;
}
__device__ __forceinline__ void lds_v2u64(uint64_t& a, uint64_t& b, uint32_t off) {
    asm("ld.shared.v2.u64 {%0, %1}, [%2];" : "=l"(a), "=l"(b) : "r"(off));
}

// ---------- zero kernel (stream B, before edge) ----------
__global__ void zero_kernel() {
    int i = blockIdx.x * blockDim.x + threadIdx.x;
    if (i < N_NODES) { g_deg[i] = 0.f; g_sw[i] = 0.f; }
}

// ---------- edge kernel: 4 edges/thread ----------
__global__ void edge_kernel(const int* __restrict__ ei,
                            const float* __restrict__ ew) {
    int t4 = blockIdx.x * blockDim.x + threadIdx.x;
    if (t4 < NE / 4) {
        int4   v4 = *(const int4*)(ei + NE + 4 * t4);   // edge_index row 1
        float4 w4 = *(const float4*)(ew + 4 * t4);
        if ((unsigned)v4.x < N_NODES) { atomicAdd(&g_deg[v4.x], 1.0f); atomicAdd(&g_sw[v4.x], w4.x); }
        if ((unsigned)v4.y < N_NODES) { atomicAdd(&g_deg[v4.y], 1.0f); atomicAdd(&g_sw[v4.y], w4.y); }
        if ((unsigned)v4.z < N_NODES) { atomicAdd(&g_deg[v4.z], 1.0f); atomicAdd(&g_sw[v4.z], w4.z); }
        if ((unsigned)v4.w < N_NODES) { atomicAdd(&g_deg[v4.w], 1.0f); atomicAdd(&g_sw[v4.w], w4.w); }
    }
}

// ---------- trans kernel (main stream): transMu + c3 + transW ----------
__global__ void __launch_bounds__(256)
trans_kernel(const float* __restrict__ mu, const float* __restrict__ W2,
             const float* __restrict__ W7, const float* __restrict__ W3,
             const float* __restrict__ W4) {
    __shared__ float S[64][65];
    int b = blockIdx.x;
    int tid = threadIdx.x;

    if (b < 782) {                       // transMu (64-row tiles)
        int v0 = b * 64;
#pragma unroll
        for (int s = 0; s < 16; s++) {
            int j = tid + 256 * s;
            int r = j >> 6, k = j & 63;
            int v = v0 + r;
            S[r][k] = (v < N_NODES) ? mu[v * 64 + k] : 0.f;
        }
        __syncthreads();
#pragma unroll
        for (int s = 0; s < 16; s++) {
            int j = tid + 256 * s;
            int k = j >> 6, r = j & 63;
            g_muT[k][v0 + r] = S[r][k];
        }
    } else if (b == 782) {               // c3 + zero g_S
        int t = tid >> 6, h = tid & 63;
        S[t][h] = fmaxf(W4[t * HD + h], 0.f);
        if (tid < 64) g_S[tid] = 0.f;
        __syncthreads();
        float s = 0.f;
        const float* row = W3 + t * HD * HD + h * HD;
#pragma unroll 16
        for (int k = 0; k < HD; k++) s = fmaf(row[k], S[t][k], s);
        g_c3[t * HD + h] = s;
    } else {                             // transW, layers 0..4
        int l = b - 783;
        const float* src = (l < 4) ? (W2 + l * 4096) : W7;
#pragma unroll
        for (int s = 0; s < 16; s++) {
            int j = tid + 256 * s;
            S[j >> 6][j & 63] = src[j];
        }
        __syncthreads();
#pragma unroll
        for (int s = 0; s < 16; s++) {
            int j = tid + 256 * s;
            g_WT[l][j >> 6][j & 63] = S[j & 63][j >> 6];
        }
    }
}

// ---------- fused kernel: 4 S2V steps + readout; 64-node tile, 256 threads ----------
// Thread tile: 4 cols (c0=4*(tid>>4)) x 4 rows (r0=4*(tid&15)).
// m-operands loaded pre-packed via ld.shared.v2.u64; weights broadcast float4.
__global__ void __launch_bounds__(256, 5)
fused_kernel(const float* __restrict__ x,
             const float* __restrict__ W1,
             const float* __restrict__ W5,
             float* __restrict__ out) {
    __shared__ __align__(16) float Ws[HD][WSTRIDE];
    __shared__ __align__(16) float muT[HD][RSTRIDE];
    __shared__ float xs[64], degs[64], sws[64];
    __shared__ float w1s[64], c3s[64];
    __shared__ float colp[4][64];

    float (*red)[17] = (float (*)[17])&muT[0][0];   // alias (muT dead at use)

    const int tid = threadIdx.x;
    const int cx = tid >> 4;       // 0..15
    const int qy = tid & 15;       // 0..15
    const int c0 = cx * 4;
    const int r0 = qy * 4;
    const int v0 = blockIdx.x * 64;

    const uint32_t mu_base = sptr(&muT[0][0]);
    const uint32_t moff0   = mu_base + r0 * 4;
    const uint32_t mrow    = RSTRIDE * 4;

    // stage mu tile: straight float4 copies (1024 float4, 4/thread)
#pragma unroll
    for (int s = 0; s < 4; s++) {
        int j = tid + 256 * s;
        int k = j >> 4, q = j & 15;
        *(float4*)&muT[k][4 * q] = *(const float4*)&g_muT[k][v0 + 4 * q];
    }
    if (tid < 64) {
        int v = v0 + tid;
        xs[tid]   = (v < N_NODES) ? x[v]     : 0.f;
        degs[tid] = (v < N_NODES) ? g_deg[v] : 0.f;
        sws[tid]  = (v < N_NODES) ? g_sw[v]  : 0.f;
    }

#pragma unroll 1
    for (int t = 0; t < TSTEPS; t++) {
        __syncthreads();
#pragma unroll
        for (int s = 0; s < 4; s++) {
            int j = tid + 256 * s;
            int k = j >> 4, q = j & 15;
            *(float4*)&Ws[k][4 * q] = *(const float4*)&g_WT[t][k][4 * q];
        }
        if (tid < 64) { w1s[tid] = W1[t * 64 + tid]; c3s[tid] = g_c3[t * 64 + tid]; }
        __syncthreads();

        uint64_t acc[4][2];   // [col i][row pair]
#pragma unroll
        for (int i = 0; i < 4; i++) { acc[i][0] = 0ULL; acc[i][1] = 0ULL; }

        uint32_t moff = moff0;
#pragma unroll 8
        for (int k = 0; k < 64; k++) {
            uint64_t a01, a23;
            lds_v2u64(a01, a23, moff);
            moff += mrow;
            float4 w = *(const float4*)&Ws[k][c0];   // broadcast (2 addrs/warp)
            uint64_t wp;
            wp = splat2(w.x); ffma2(acc[0][0], a01, wp); ffma2(acc[0][1], a23, wp);
            wp = splat2(w.y); ffma2(acc[1][0], a01, wp); ffma2(acc[1][1], a23, wp);
            wp = splat2(w.z); ffma2(acc[2][0], a01, wp); ffma2(acc[2][1], a23, wp);
            wp = splat2(w.w); ffma2(acc[3][0], a01, wp); ffma2(acc[3][1], a23, wp);
        }
        __syncthreads();

        // epilogue: mu' = relu(x*w1 + deg*acc + sw*c3)
        float x0 = xs[r0], x1 = xs[r0+1], x2 = xs[r0+2], x3 = xs[r0+3];
        float d0 = degs[r0], d1 = degs[r0+1], d2 = degs[r0+2], d3 = degs[r0+3];
        float s0 = sws[r0], s1 = sws[r0+1], s2 = sws[r0+2], s3 = sws[r0+3];
#pragma unroll
        for (int i = 0; i < 4; i++) {
            int c = c0 + i;
            float w1c = w1s[c], c3c = c3s[c];
            float2 p0 = unpack2(acc[i][0]);
            float2 p1 = unpack2(acc[i][1]);
            float4 o;
            o.x = fmaxf(fmaf(x0, w1c, fmaf(d0, p0.x, s0 * c3c)), 0.f);
            o.y = fmaxf(fmaf(x1, w1c, fmaf(d1, p0.y, s1 * c3c)), 0.f);
            o.z = fmaxf(fmaf(x2, w1c, fmaf(d2, p1.x, s2 * c3c)), 0.f);
            o.w = fmaxf(fmaf(x3, w1c, fmaf(d3, p1.y, s3 * c3c)), 0.f);
            *(float4*)&muT[c][r0] = o;
        }
    }
    __syncthreads();

    // graph-pool column partials
    {
        int h = tid & 63, g = tid >> 6;
        float s = 0.f;
#pragma unroll
        for (int j = 0; j < 16; j++) s += muT[h][g * 16 + j];
        colp[g][h] = s;
    }
    // stage W7^T and W5 node-half
#pragma unroll
    for (int s = 0; s < 4; s++) {
        int j = tid + 256 * s;
        int k = j >> 4, q = j & 15;
        *(float4*)&Ws[k][4 * q] = *(const float4*)&g_WT[4][k][4 * q];
    }
    if (tid < 64) w1s[tid] = W5[64 + tid];
    __syncthreads();

    if (tid < 64)
        atomicAdd(&g_S[tid], colp[0][tid] + colp[1][tid] + colp[2][tid] + colp[3][tid]);

    // final GEMM: nodes_vec = mu @ W7^T
    uint64_t acc[4][2];
#pragma unroll
    for (int i = 0; i < 4; i++) { acc[i][0] = 0ULL; acc[i][1] = 0ULL; }

    uint32_t moff = moff0;
#pragma unroll 8
    for (int k = 0; k < 64; k++) {
        uint64_t a01, a23;
        lds_v2u64(a01, a23, moff);
        moff += mrow;
        float4 w = *(const float4*)&Ws[k][c0];
        uint64_t wp;
        wp = splat2(w.x); ffma2(acc[0][0], a01, wp); ffma2(acc[0][1], a23, wp);
        wp = splat2(w.y); ffma2(acc[1][0], a01, wp); ffma2(acc[1][1], a23, wp);
        wp = splat2(w.z); ffma2(acc[2][0], a01, wp); ffma2(acc[2][1], a23, wp);
        wp = splat2(w.w); ffma2(acc[3][0], a01, wp); ffma2(acc[3][1], a23, wp);
    }

    float pr[4] = {0.f, 0.f, 0.f, 0.f};
#pragma unroll
    for (int i = 0; i < 4; i++) {
        float wb = w1s[c0 + i];
        float2 p0 = unpack2(acc[i][0]);
        float2 p1 = unpack2(acc[i][1]);
        pr[0] = fmaf(fmaxf(p0.x, 0.f), wb, pr[0]);
        pr[1] = fmaf(fmaxf(p0.y, 0.f), wb, pr[1]);
        pr[2] = fmaf(fmaxf(p1.x, 0.f), wb, pr[2]);
        pr[3] = fmaf(fmaxf(p1.y, 0.f), wb, pr[3]);
    }
    __syncthreads();   // muT reads done -> safe to write red alias
#pragma unroll
    for (int j = 0; j < 4; j++)
        red[r0 + j][cx] = pr[j];
    __syncthreads();

    if (tid < 64) {
        float s = 0.f;
#pragma unroll
        for (int q = 0; q < 16; q++) s += red[tid][q];
        int v = v0 + tid;
        if (v < N_NODES) out[v] = s;
    }
}

// graph-pool scalar + broadcast add
__global__ void add_kernel(const float* __restrict__ W5, float* __restrict__ out) {
    __shared__ float sh[64];
    __shared__ float cval;
    int tid = threadIdx.x;
    if (tid < 64) sh[tid] = fmaxf(g_S[tid], 0.f) * W5[tid];
    __syncthreads();
    if (tid == 0) {
        float s = 0.f;
#pragma unroll
        for (int i = 0; i < 64; i++) s += sh[i];
        cval = s;
    }
    __syncthreads();
    int v = blockIdx.x * blockDim.x + tid;
    if (v < N_NODES) out[v] += cval;
}

// ---------- launch (fork-join: [zero->edge] || [trans], then fused, add) ----------
extern "C" void kernel_launch(void* const* d_in, const int* in_sizes, int n_in,
                              void* d_out, int out_size) {
    const float* mu = (const float*)d_in[0];
    const float* x  = (const float*)d_in[1];
    const int*   ei = (const int*)d_in[2];     // int32 (JAX x64 disabled)
    const float* ew = (const float*)d_in[3];
    const float* W1 = (const float*)d_in[4];
    const float* W2 = (const float*)d_in[5];
    const float* W3 = (const float*)d_in[6];
    const float* W4 = (const float*)d_in[7];
    const float* W5 = (const float*)d_in[8];
    const float* W7 = (const float*)d_in[9];
    float* out = (float*)d_out;

    cudaStream_t s1;
    cudaEvent_t ev0, ev1;
    cudaStreamCreateWithFlags(&s1, cudaStreamNonBlocking);
    cudaEventCreateWithFlags(&ev0, cudaEventDisableTiming);
    cudaEventCreateWithFlags(&ev1, cudaEventDisableTiming);

    // fork: side stream does zero -> edge
    cudaEventRecord(ev0, 0);
    cudaStreamWaitEvent(s1, ev0, 0);
    zero_kernel<<<(N_NODES + 255) / 256, 256, 0, s1>>>();
    edge_kernel<<<(NE / 4 + 255) / 256, 256, 0, s1>>>(ei, ew);
    cudaEventRecord(ev1, s1);

    // main stream does transposes concurrently
    trans_kernel<<<788, 256>>>(mu, W2, W7, W3, W4);

    // join, then fused + add on main stream
    cudaStreamWaitEvent(0, ev1, 0);
    fused_kernel<<<NPAD / 64, 256>>>(x, W1, W5, out);
    add_kernel<<<(N_NODES + 255) / 256, 256>>>(W5, out);
}

// round 12
// speedup vs baseline: 1.0138x; 1.0138x over previous
#include <cuda_runtime.h>
#include <cstdint>

#define N_NODES 50000
#define NPAD    50048   // 64*782
#define NE      800000
#define HD      64
#define TSTEPS  4
#define RSTRIDE 68      // muT row stride (floats)
#define WSTRIDE 68      // Ws row stride (floats)

// ---------- device scratch ----------
__device__ float g_deg[N_NODES];
__device__ float g_sw[N_NODES];
__device__ float g_c3[TSTEPS * HD];
__device__ float g_S[HD];
__device__ float g_WT[5][HD][HD];      // [0..3]=W2[t]^T, [4]=W7^T
__device__ float g_muT[HD][NPAD];      // transposed mu

// ---------- f32x2 helpers ----------
__device__ __forceinline__ void ffma2(uint64_t& acc, uint64_t a, uint64_t b) {
    asm("fma.rn.f32x2 %0, %1, %2, %0;" : "+l"(acc) : "l"(a), "l"(b));
}
__device__ __forceinline__ uint64_t splat2(float v) {
    uint64_t r;
    asm("mov.b64 %0, {%1, %1};" : "=l"(r) : "f"(v));
    return r;
}
__device__ __forceinline__ float2 unpack2(uint64_t v) {
    float lo, hi;
    asm("mov.b64 {%0, %1}, %2;" : "=f"(lo), "=f"(hi) : "l"(v));
    return make_float2(lo, hi);
}
__device__ __forceinline__ uint32_t sptr(const void* p) {
    uint32_t r;
    asm("{.reg .u64 t; cvta.to.shared.u64 t, %1; cvt.u32.u64 %0, t;}"
        : "=r"(r) : "l"(p));
    return r;
}
__device__ __forceinline__ void lds_v2u64(uint64_t& a, uint64_t& b, uint32_t off) {
    asm("ld.shared.v2.u64 {%0, %1}, [%2];" : "=l"(a), "=l"(b) : "r"(off));
}
__device__ __forceinline__ void lds_v4f32(float4& m, uint32_t off) {
    asm("ld.shared.v4.b32 {%0,%1,%2,%3}, [%4];"
        : "=f"(m.x), "=f"(m.y), "=f"(m.z), "=f"(m.w) : "r"(off));
}

// ---------- zero kernel (stream B, before edge) ----------
__global__ void zero_kernel() {
    int i = blockIdx.x * blockDim.x + threadIdx.x;
    if (i < N_NODES) { g_deg[i] = 0.f; g_sw[i] = 0.f; }
}

// ---------- edge kernel: 4 edges/thread ----------
__global__ void edge_kernel(const int* __restrict__ ei,
                            const float* __restrict__ ew) {
    int t4 = blockIdx.x * blockDim.x + threadIdx.x;
    if (t4 < NE / 4) {
        int4   v4 = *(const int4*)(ei + NE + 4 * t4);   // edge_index row 1
        float4 w4 = *(const float4*)(ew + 4 * t4);
        if ((unsigned)v4.x < N_NODES) { atomicAdd(&g_deg[v4.x], 1.0f); atomicAdd(&g_sw[v4.x], w4.x); }
        if ((unsigned)v4.y < N_NODES) { atomicAdd(&g_deg[v4.y], 1.0f); atomicAdd(&g_sw[v4.y], w4.y); }
        if ((unsigned)v4.z < N_NODES) { atomicAdd(&g_deg[v4.z], 1.0f); atomicAdd(&g_sw[v4.z], w4.z); }
        if ((unsigned)v4.w < N_NODES) { atomicAdd(&g_deg[v4.w], 1.0f); atomicAdd(&g_sw[v4.w], w4.w); }
    }
}

// ---------- trans kernel: transMu + c3 + transW ----------
__global__ void __launch_bounds__(256)
trans_kernel(const float* __restrict__ mu, const float* __restrict__ W2,
             const float* __restrict__ W7, const float* __restrict__ W3,
             const float* __restrict__ W4) {
    __shared__ float S[64][65];
    int b = blockIdx.x;
    int tid = threadIdx.x;

    if (b < 782) {                       // transMu (64-row tiles)
        int v0 = b * 64;
#pragma unroll
        for (int s = 0; s < 16; s++) {
            int j = tid + 256 * s;
            int r = j >> 6, k = j & 63;
            int v = v0 + r;
            S[r][k] = (v < N_NODES) ? mu[v * 64 + k] : 0.f;
        }
        __syncthreads();
#pragma unroll
        for (int s = 0; s < 16; s++) {
            int j = tid + 256 * s;
            int k = j >> 6, r = j & 63;
            g_muT[k][v0 + r] = S[r][k];
        }
    } else if (b == 782) {               // c3 + zero g_S
        int t = tid >> 6, h = tid & 63;
        S[t][h] = fmaxf(W4[t * HD + h], 0.f);
        if (tid < 64) g_S[tid] = 0.f;
        __syncthreads();
        float s = 0.f;
        const float* row = W3 + t * HD * HD + h * HD;
#pragma unroll 16
        for (int k = 0; k < HD; k++) s = fmaf(row[k], S[t][k], s);
        g_c3[t * HD + h] = s;
    } else {                             // transW, layers 0..4
        int l = b - 783;
        const float* src = (l < 4) ? (W2 + l * 4096) : W7;
#pragma unroll
        for (int s = 0; s < 16; s++) {
            int j = tid + 256 * s;
            S[j >> 6][j & 63] = src[j];
        }
        __syncthreads();
#pragma unroll
        for (int s = 0; s < 16; s++) {
            int j = tid + 256 * s;
            g_WT[l][j >> 6][j & 63] = S[j & 63][j >> 6];
        }
    }
}

// ---------- fused kernel: 4 S2V steps + readout ----------
// 64-node tile, 128 threads. Thread tile: 4 rows (r0=4*(tid>>3)) x 8 cols
// ({4tx..4tx+3} U {32+4tx..32+4tx+3}). Weights loaded as u64 col-pairs
// (conflict-free 16B stride); m float4 broadcast (1 wf), splatted per row.
__global__ void __launch_bounds__(128, 6)
fused_kernel(const float* __restrict__ x,
             const float* __restrict__ W1,
             const float* __restrict__ W5,
             float* __restrict__ out) {
    __shared__ __align__(16) float Ws[HD][WSTRIDE];
    __shared__ __align__(16) float muT[HD][RSTRIDE];
    __shared__ float xs[64], degs[64], sws[64];
    __shared__ float w1s[64], c3s[64];
    __shared__ float colp[2][64];

    float (*red)[9] = (float (*)[9])&muT[0][0];   // alias (muT dead at use)

    const int tid = threadIdx.x;
    const int tx = tid & 7;        // col chunk 0..7
    const int qy = tid >> 3;       // row group 0..15
    const int cA = tx * 4;         // cols cA..cA+3
    const int cB = 32 + tx * 4;    // cols cB..cB+3
    const int r0 = qy * 4;
    const int v0 = blockIdx.x * 64;

    const uint32_t mu_base = sptr(&muT[0][0]);
    const uint32_t ws_base = sptr(&Ws[0][0]);
    const uint32_t moff0   = mu_base + r0 * 4;
    const uint32_t woffA0  = ws_base + cA * 4;
    const uint32_t woffB0  = ws_base + cB * 4;
    const uint32_t mrow    = RSTRIDE * 4;
    const uint32_t wrow    = WSTRIDE * 4;

    // stage mu tile (1024 float4, 8/thread)
#pragma unroll
    for (int s = 0; s < 8; s++) {
        int j = tid + 128 * s;
        int k = j >> 4, q = j & 15;
        *(float4*)&muT[k][4 * q] = *(const float4*)&g_muT[k][v0 + 4 * q];
    }
    if (tid < 64) {
        int v = v0 + tid;
        xs[tid]   = (v < N_NODES) ? x[v]     : 0.f;
        degs[tid] = (v < N_NODES) ? g_deg[v] : 0.f;
        sws[tid]  = (v < N_NODES) ? g_sw[v]  : 0.f;
    }

#pragma unroll 1
    for (int t = 0; t < TSTEPS; t++) {
        __syncthreads();
#pragma unroll
        for (int s = 0; s < 8; s++) {
            int j = tid + 128 * s;
            int k = j >> 4, q = j & 15;
            *(float4*)&Ws[k][4 * q] = *(const float4*)&g_WT[t][k][4 * q];
        }
        if (tid < 64) { w1s[tid] = W1[t * 64 + tid]; c3s[tid] = g_c3[t * 64 + tid]; }
        __syncthreads();

        // acc[p][r]: p=0:(cA,cA+1) 1:(cA+2,cA+3) 2:(cB,cB+1) 3:(cB+2,cB+3)
        uint64_t acc[4][4];
#pragma unroll
        for (int p = 0; p < 4; p++)
#pragma unroll
            for (int r = 0; r < 4; r++) acc[p][r] = 0ULL;

        uint32_t moff = moff0, woffA = woffA0, woffB = woffB0;
#pragma unroll 8
        for (int k = 0; k < 64; k++) {
            uint64_t wA0, wA1, wB0, wB1;
            lds_v2u64(wA0, wA1, woffA);
            lds_v2u64(wB0, wB1, woffB);
            float4 m;
            lds_v4f32(m, moff);
            moff += mrow; woffA += wrow; woffB += wrow;
            uint64_t m0 = splat2(m.x), m1 = splat2(m.y),
                     m2 = splat2(m.z), m3 = splat2(m.w);
            ffma2(acc[0][0], wA0, m0); ffma2(acc[0][1], wA0, m1);
            ffma2(acc[0][2], wA0, m2); ffma2(acc[0][3], wA0, m3);
            ffma2(acc[1][0], wA1, m0); ffma2(acc[1][1], wA1, m1);
            ffma2(acc[1][2], wA1, m2); ffma2(acc[1][3], wA1, m3);
            ffma2(acc[2][0], wB0, m0); ffma2(acc[2][1], wB0, m1);
            ffma2(acc[2][2], wB0, m2); ffma2(acc[2][3], wB0, m3);
            ffma2(acc[3][0], wB1, m0); ffma2(acc[3][1], wB1, m1);
            ffma2(acc[3][2], wB1, m2); ffma2(acc[3][3], wB1, m3);
        }
        __syncthreads();

        // epilogue: mu' = relu(x*w1 + deg*acc + sw*c3); store col-major float4
        float xr[4], dr[4], sr[4];
#pragma unroll
        for (int r = 0; r < 4; r++) {
            xr[r] = xs[r0 + r]; dr[r] = degs[r0 + r]; sr[r] = sws[r0 + r];
        }
#pragma unroll
        for (int p = 0; p < 4; p++) {
            int c = (p < 2) ? (cA + 2 * p) : (cB + 2 * (p - 2));
            float w1a = w1s[c],     c3a = c3s[c];
            float w1b = w1s[c + 1], c3b = c3s[c + 1];
            float4 oa, ob;
            float2 q0 = unpack2(acc[p][0]);
            float2 q1 = unpack2(acc[p][1]);
            float2 q2 = unpack2(acc[p][2]);
            float2 q3 = unpack2(acc[p][3]);
            oa.x = fmaxf(fmaf(xr[0], w1a, fmaf(dr[0], q0.x, sr[0] * c3a)), 0.f);
            oa.y = fmaxf(fmaf(xr[1], w1a, fmaf(dr[1], q1.x, sr[1] * c3a)), 0.f);
            oa.z = fmaxf(fmaf(xr[2], w1a, fmaf(dr[2], q2.x, sr[2] * c3a)), 0.f);
            oa.w = fmaxf(fmaf(xr[3], w1a, fmaf(dr[3], q3.x, sr[3] * c3a)), 0.f);
            ob.x = fmaxf(fmaf(xr[0], w1b, fmaf(dr[0], q0.y, sr[0] * c3b)), 0.f);
            ob.y = fmaxf(fmaf(xr[1], w1b, fmaf(dr[1], q1.y, sr[1] * c3b)), 0.f);
            ob.z = fmaxf(fmaf(xr[2], w1b, fmaf(dr[2], q2.y, sr[2] * c3b)), 0.f);
            ob.w = fmaxf(fmaf(xr[3], w1b, fmaf(dr[3], q3.y, sr[3] * c3b)), 0.f);
            *(float4*)&muT[c][r0]     = oa;
            *(float4*)&muT[c + 1][r0] = ob;
        }
    }
    __syncthreads();

    // graph-pool column partials (h = tid&63, half g = tid>>6)
    {
        int h = tid & 63, g = tid >> 6;
        float s = 0.f;
#pragma unroll
        for (int j = 0; j < 32; j++) s += muT[h][g * 32 + j];
        colp[g][h] = s;
    }
    // stage W7^T and W5 node-half
#pragma unroll
    for (int s = 0; s < 8; s++) {
        int j = tid + 128 * s;
        int k = j >> 4, q = j & 15;
        *(float4*)&Ws[k][4 * q] = *(const float4*)&g_WT[4][k][4 * q];
    }
    if (tid < 64) w1s[tid] = W5[64 + tid];
    __syncthreads();

    if (tid < 64)
        atomicAdd(&g_S[tid], colp[0][tid] + colp[1][tid]);

    // final GEMM: nodes_vec = mu @ W7^T
    uint64_t acc[4][4];
#pragma unroll
    for (int p = 0; p < 4; p++)
#pragma unroll
        for (int r = 0; r < 4; r++) acc[p][r] = 0ULL;

    uint32_t moff = moff0, woffA = woffA0, woffB = woffB0;
#pragma unroll 8
    for (int k = 0; k < 64; k++) {
        uint64_t wA0, wA1, wB0, wB1;
        lds_v2u64(wA0, wA1, woffA);
        lds_v2u64(wB0, wB1, woffB);
        float4 m;
        lds_v4f32(m, moff);
        moff += mrow; woffA += wrow; woffB += wrow;
        uint64_t m0 = splat2(m.x), m1 = splat2(m.y),
                 m2 = splat2(m.z), m3 = splat2(m.w);
        ffma2(acc[0][0], wA0, m0); ffma2(acc[0][1], wA0, m1);
        ffma2(acc[0][2], wA0, m2); ffma2(acc[0][3], wA0, m3);
        ffma2(acc[1][0], wA1, m0); ffma2(acc[1][1], wA1, m1);
        ffma2(acc[1][2], wA1, m2); ffma2(acc[1][3], wA1, m3);
        ffma2(acc[2][0], wB0, m0); ffma2(acc[2][1], wB0, m1);
        ffma2(acc[2][2], wB0, m2); ffma2(acc[2][3], wB0, m3);
        ffma2(acc[3][0], wB1, m0); ffma2(acc[3][1], wB1, m1);
        ffma2(acc[3][2], wB1, m2); ffma2(acc[3][3], wB1, m3);
    }

    // per-row partial of sum_c relu(nv)*W5b[c]
    float pr[4] = {0.f, 0.f, 0.f, 0.f};
#pragma unroll
    for (int p = 0; p < 4; p++) {
        int c = (p < 2) ? (cA + 2 * p) : (cB + 2 * (p - 2));
        float wa = w1s[c], wb = w1s[c + 1];
#pragma unroll
        for (int r = 0; r < 4; r++) {
            float2 q = unpack2(acc[p][r]);
            pr[r] = fmaf(fmaxf(q.x, 0.f), wa, fmaf(fmaxf(q.y, 0.f), wb, pr[r]));
        }
    }
    __syncthreads();   // muT reads done -> safe to write red alias
#pragma unroll
    for (int r = 0; r < 4; r++)
        red[r0 + r][tx] = pr[r];
    __syncthreads();

    if (tid < 64) {
        float s = 0.f;
#pragma unroll
        for (int q = 0; q < 8; q++) s += red[tid][q];
        int v = v0 + tid;
        if (v < N_NODES) out[v] = s;
    }
}

// graph-pool scalar + broadcast add
__global__ void add_kernel(const float* __restrict__ W5, float* __restrict__ out) {
    __shared__ float sh[64];
    __shared__ float cval;
    int tid = threadIdx.x;
    if (tid < 64) sh[tid] = fmaxf(g_S[tid], 0.f) * W5[tid];
    __syncthreads();
    if (tid == 0) {
        float s = 0.f;
#pragma unroll
        for (int i = 0; i < 64; i++) s += sh[i];
        cval = s;
    }
    __syncthreads();
    int v = blockIdx.x * blockDim.x + tid;
    if (v < N_NODES) out[v] += cval;
}

// ---------- launch (fork-join: [zero->edge] || [trans], then fused, add) ----------
extern "C" void kernel_launch(void* const* d_in, const int* in_sizes, int n_in,
                              void* d_out, int out_size) {
    const float* mu = (const float*)d_in[0];
    const float* x  = (const float*)d_in[1];
    const int*   ei = (const int*)d_in[2];     // int32 (JAX x64 disabled)
    const float* ew = (const float*)d_in[3];
    const float* W1 = (const float*)d_in[4];
    const float* W2 = (const float*)d_in[5];
    const float* W3 = (const float*)d_in[6];
    const float* W4 = (const float*)d_in[7];
    const float* W5 = (const float*)d_in[8];
    const float* W7 = (const float*)d_in[9];
    float* out = (float*)d_out;

    cudaStream_t s1;
    cudaEvent_t ev0, ev1;
    cudaStreamCreateWithFlags(&s1, cudaStreamNonBlocking);
    cudaEventCreateWithFlags(&ev0, cudaEventDisableTiming);
    cudaEventCreateWithFlags(&ev1, cudaEventDisableTiming);

    cudaEventRecord(ev0, 0);
    cudaStreamWaitEvent(s1, ev0, 0);
    zero_kernel<<<(N_NODES + 255) / 256, 256, 0, s1>>>();
    edge_kernel<<<(NE / 4 + 255) / 256, 256, 0, s1>>>(ei, ew);
    cudaEventRecord(ev1, s1);

    trans_kernel<<<788, 256>>>(mu, W2, W7, W3, W4);

    cudaStreamWaitEvent(0, ev1, 0);
    fused_kernel<<<NPAD / 64, 128>>>(x, W1, W5, out);
    add_kernel<<<(N_NODES + 255) / 256, 256>>>(W5, out);
}

// round 16
// speedup vs baseline: 1.4104x; 1.3912x over previous
#include <cuda_runtime.h>
#include <cstdint>

#define N_NODES 50000
#define NE      800000
#define HD      64
#define GRID_F  782          // 782 * 64 = 50048 rows

// ---------- device scratch ----------
__device__ float g_deg[N_NODES];
__device__ float g_sw[N_NODES];
__device__ float g_c3[4 * HD];
__device__ float g_S[HD];
// B fragments, mma.m16n8k16 col-layout order: [layer][h/m/l][frag=ntile*4+kstep][lane]
__device__ uint2 g_Bfrag[5][3][32][32];

// ---------- helpers ----------
__device__ __forceinline__ uint32_t sptr(const void* p) {
    uint32_t r;
    asm("{.reg .u64 t; cvta.to.shared.u64 t, %1; cvt.u32.u64 %0, t;}"
        : "=r"(r) : "l"(p));
    return r;
}
__device__ __forceinline__ void lds_v2u32(uint32_t& a, uint32_t& b, uint32_t off) {
    asm("ld.shared.v2.b32 {%0, %1}, [%2];" : "=r"(a), "=r"(b) : "r"(off));
}
__device__ __forceinline__ uint32_t bf_rn(float v) {      // top 16 bits, RN
    return (__float_as_uint(v) + 0x8000u) & 0xFFFF0000u;
}
// 3-way split: v == h + m + l EXACTLY for fp32 v. Pack pairs as bf16x2.
__device__ __forceinline__ void split3_pack(float a, float b,
                                            uint32_t& h, uint32_t& m, uint32_t& l) {
    uint32_t ha = bf_rn(a), hb = bf_rn(b);
    float ra = a - __uint_as_float(ha);        // exact
    float rb = b - __uint_as_float(hb);
    uint32_t ma = bf_rn(ra), mb = bf_rn(rb);
    float la = ra - __uint_as_float(ma);       // exact, fits bf16 exactly
    float lb = rb - __uint_as_float(mb);
    h = (ha >> 16) | hb;
    m = (ma >> 16) | mb;
    l = ((__float_as_uint(la) & 0xFFFF0000u) >> 16) |
        (__float_as_uint(lb) & 0xFFFF0000u);
}
__device__ __forceinline__ void mma_bf16(float c[4],
                                         const uint32_t a[4],
                                         uint32_t b0, uint32_t b1) {
    asm volatile(
        "mma.sync.aligned.m16n8k16.row.col.f32.bf16.bf16.f32 "
        "{%0,%1,%2,%3}, {%4,%5,%6,%7}, {%8,%9}, {%0,%1,%2,%3};"
        : "+f"(c[0]), "+f"(c[1]), "+f"(c[2]), "+f"(c[3])
        : "r"(a[0]), "r"(a[1]), "r"(a[2]), "r"(a[3]), "r"(b0), "r"(b1));
}

// ---------- small kernels ----------
__global__ void zero_kernel() {
    int i = blockIdx.x * blockDim.x + threadIdx.x;
    if (i < N_NODES) { g_deg[i] = 0.f; g_sw[i] = 0.f; }
}

__global__ void edge_kernel(const int* __restrict__ ei,
                            const float* __restrict__ ew) {
    int t4 = blockIdx.x * blockDim.x + threadIdx.x;
    if (t4 < NE / 4) {
        int4   v4 = *(const int4*)(ei + NE + 4 * t4);   // edge_index row 1 (int32)
        float4 w4 = *(const float4*)(ew + 4 * t4);
        if ((unsigned)v4.x < N_NODES) { atomicAdd(&g_deg[v4.x], 1.0f); atomicAdd(&g_sw[v4.x], w4.x); }
        if ((unsigned)v4.y < N_NODES) { atomicAdd(&g_deg[v4.y], 1.0f); atomicAdd(&g_sw[v4.y], w4.y); }
        if ((unsigned)v4.z < N_NODES) { atomicAdd(&g_deg[v4.z], 1.0f); atomicAdd(&g_sw[v4.z], w4.z); }
        if ((unsigned)v4.w < N_NODES) { atomicAdd(&g_deg[v4.w], 1.0f); atomicAdd(&g_sw[v4.w], w4.w); }
    }
}

// prep: b==0 -> c3 + zero g_S ; b 1..15 -> B fragments (layer, h/m/l)
__global__ void __launch_bounds__(256)
prep_kernel(const float* __restrict__ W2, const float* __restrict__ W7,
            const float* __restrict__ W3, const float* __restrict__ W4) {
    int b = blockIdx.x, tid = threadIdx.x;
    if (b == 0) {
        __shared__ float rw4[4][64];
        int t = tid >> 6, h = tid & 63;
        rw4[t][h] = fmaxf(W4[t * HD + h], 0.f);
        if (tid < 64) g_S[tid] = 0.f;
        __syncthreads();
        float s = 0.f;
        const float* row = W3 + t * HD * HD + h * HD;
#pragma unroll 16
        for (int k = 0; k < HD; k++) s = fmaf(row[k], rw4[t][k], s);
        g_c3[t * HD + h] = s;
    } else {
        int l  = (b - 1) / 3;           // layer 0..4
        int hl = (b - 1) % 3;           // 0=h 1=m 2=l
        const float* W = (l < 4) ? (W2 + l * 4096) : W7;
#pragma unroll
        for (int s = 0; s < 4; s++) {
            int i = tid + 256 * s;      // 0..1023 = frag*32 + lane
            int frag = i >> 5, lane = i & 31;
            int ntile = frag >> 2, kstep = frag & 3;
            int m = lane & 3;
            int n = ntile * 8 + (lane >> 2);
            int k0 = kstep * 16 + 2 * m;
            float w00 = W[n * 64 + k0],     w01 = W[n * 64 + k0 + 1];
            float w10 = W[n * 64 + k0 + 8], w11 = W[n * 64 + k0 + 9];
            uint32_t h0, m0, l0, h1, m1, l1;
            split3_pack(w00, w01, h0, m0, l0);
            split3_pack(w10, w11, h1, m1, l1);
            uint2 val = (hl == 0) ? make_uint2(h0, h1)
                      : (hl == 1) ? make_uint2(m0, m1)
                                  : make_uint2(l0, l1);
            g_Bfrag[l][hl][frag][lane] = val;
        }
    }
}

// ---------- fused HMMA kernel: 64 nodes/CTA, 128 threads, warp owns 16 rows ----------
__global__ void __launch_bounds__(128, 4)
fused_kernel(const float* __restrict__ mu, const float* __restrict__ x,
             const float* __restrict__ W1, const float* __restrict__ W5,
             float* __restrict__ out) {
    __shared__ uint2  sB[3][32][32];    // 24KB: [h/m/l][frag][lane]
    __shared__ float2 wc[64];           // (w1, c3) per col
    __shared__ float  w5b[64];
    __shared__ float  colp[4][64];

    const int tid  = threadIdx.x;
    const int wid  = tid >> 5;
    const int lane = tid & 31;
    const int m    = lane & 3;
    const int rg   = lane >> 2;
    const int v0   = blockIdx.x * 64;
    const int vr   = v0 + wid * 16 + rg;     // row r
    const int vr8  = vr + 8;                 // row r+8
    const bool okr  = vr  < N_NODES;
    const bool okr8 = vr8 < N_NODES;

    const float deg_r  = okr  ? g_deg[vr]  : 0.f;
    const float deg_r8 = okr8 ? g_deg[vr8] : 0.f;
    const float sw_r   = okr  ? g_sw[vr]   : 0.f;
    const float sw_r8  = okr8 ? g_sw[vr8]  : 0.f;
    const float x_r    = okr  ? x[vr]      : 0.f;
    const float x_r8   = okr8 ? x[vr8]     : 0.f;

    // A fragments (3-way split). a[0]=(r,k0k1) a[1]=(r+8,k0k1) a[2]=(r,k0+8) a[3]=(r+8,k0+8)
    uint32_t ah[4][4], am[4][4], al[4][4];
    {
        const float2* mur  = (const float2*)(mu + (size_t)vr  * 64);
        const float2* mur8 = (const float2*)(mu + (size_t)vr8 * 64);
        const float2 z = make_float2(0.f, 0.f);
#pragma unroll
        for (int s = 0; s < 4; s++) {
            int p = (s * 16 + 2 * m) >> 1;      // float2 index of k0
            float2 a = okr  ? mur[p]      : z;
            float2 b = okr8 ? mur8[p]     : z;
            float2 c = okr  ? mur[p + 4]  : z;  // k0+8
            float2 d = okr8 ? mur8[p + 4] : z;
            split3_pack(deg_r  * a.x, deg_r  * a.y, ah[s][0], am[s][0], al[s][0]);
            split3_pack(deg_r8 * b.x, deg_r8 * b.y, ah[s][1], am[s][1], al[s][1]);
            split3_pack(deg_r  * c.x, deg_r  * c.y, ah[s][2], am[s][2], al[s][2]);
            split3_pack(deg_r8 * d.x, deg_r8 * d.y, ah[s][3], am[s][3], al[s][3]);
        }
    }

    const uint32_t sb_base = sptr(&sB[0][0][0]);

#pragma unroll 1
    for (int t = 0; t < 5; t++) {
        __syncthreads();
        // stage B fragments for layer t (1536 uint4, 12/thread)
        {
            const uint4* src = (const uint4*)&g_Bfrag[t][0][0][0];
            uint4* dst = (uint4*)&sB[0][0][0];
#pragma unroll
            for (int s = 0; s < 12; s++)
                dst[tid + 128 * s] = src[tid + 128 * s];
        }
        if (t < 4) { if (tid < 64) wc[tid] = make_float2(W1[t * 64 + tid], g_c3[t * 64 + tid]); }
        else       { if (tid < 64) w5b[tid] = W5[64 + tid]; }
        __syncthreads();

        float C[8][4];
#pragma unroll
        for (int n = 0; n < 8; n++)
#pragma unroll
            for (int j = 0; j < 4; j++) C[n][j] = 0.f;

#pragma unroll
        for (int n = 0; n < 8; n++) {
#pragma unroll
            for (int s = 0; s < 4; s++) {
                uint32_t off = sb_base + (uint32_t)(((n * 4 + s) * 32 + lane) * 8);
                uint32_t bh0, bh1, bm0, bm1, bl0, bl1;
                lds_v2u32(bh0, bh1, off);
                lds_v2u32(bm0, bm1, off + 8192);
                lds_v2u32(bl0, bl1, off + 16384);
                // ab = ah*bh + am*bh + ah*bm + al*bh + ah*bl + am*bm  (err ~2^-27)
                mma_bf16(C[n], ah[s], bh0, bh1);
                mma_bf16(C[n], am[s], bh0, bh1);
                mma_bf16(C[n], ah[s], bm0, bm1);
                mma_bf16(C[n], al[s], bh0, bh1);
                mma_bf16(C[n], ah[s], bl0, bl1);
                mma_bf16(C[n], am[s], bm0, bm1);
            }
        }

        if (t < 4) {
            // epilogue: C <- relu(x*w1 + C + sw*c3)   (C already carries deg factor)
#pragma unroll
            for (int n = 0; n < 8; n++) {
                int col = 8 * n + 2 * m;
                float2 w0 = wc[col], w1v = wc[col + 1];
                C[n][0] = fmaxf(fmaf(x_r,  w0.x,  fmaf(sw_r,  w0.y,  C[n][0])), 0.f);
                C[n][1] = fmaxf(fmaf(x_r,  w1v.x, fmaf(sw_r,  w1v.y, C[n][1])), 0.f);
                C[n][2] = fmaxf(fmaf(x_r8, w0.x,  fmaf(sw_r8, w0.y,  C[n][2])), 0.f);
                C[n][3] = fmaxf(fmaf(x_r8, w1v.x, fmaf(sw_r8, w1v.y, C[n][3])), 0.f);
            }
            if (t == 3) {
                // graph-pool column partials of final mu
#pragma unroll
                for (int n = 0; n < 8; n++) {
                    float sA = C[n][0] + C[n][2];
                    float sB_ = C[n][1] + C[n][3];
#pragma unroll
                    for (int o = 4; o < 32; o <<= 1) {
                        sA  += __shfl_xor_sync(0xffffffffu, sA,  o);
                        sB_ += __shfl_xor_sync(0xffffffffu, sB_, o);
                    }
                    if (lane < 4) {
                        colp[wid][8 * n + 2 * lane]     = sA;
                        colp[wid][8 * n + 2 * lane + 1] = sB_;
                    }
                }
            }
            // rebuild A for next layer (fold deg unless next layer is W7)
            float sc_r  = (t == 3) ? 1.f : deg_r;
            float sc_r8 = (t == 3) ? 1.f : deg_r8;
#pragma unroll
            for (int s = 0; s < 4; s++) {
                split3_pack(sc_r  * C[2 * s][0],     sc_r  * C[2 * s][1],     ah[s][0], am[s][0], al[s][0]);
                split3_pack(sc_r8 * C[2 * s][2],     sc_r8 * C[2 * s][3],     ah[s][1], am[s][1], al[s][1]);
                split3_pack(sc_r  * C[2 * s + 1][0], sc_r  * C[2 * s + 1][1], ah[s][2], am[s][2], al[s][2]);
                split3_pack(sc_r8 * C[2 * s + 1][2], sc_r8 * C[2 * s + 1][3], ah[s][3], am[s][3], al[s][3]);
            }
        } else {
            // readout: out[r] = sum_c relu(nv[r][c]) * W5b[c]
            float pr0 = 0.f, pr1 = 0.f;
#pragma unroll
            for (int n = 0; n < 8; n++) {
                int col = 8 * n + 2 * m;
                float wa = w5b[col], wb = w5b[col + 1];
                pr0 = fmaf(fmaxf(C[n][0], 0.f), wa, fmaf(fmaxf(C[n][1], 0.f), wb, pr0));
                pr1 = fmaf(fmaxf(C[n][2], 0.f), wa, fmaf(fmaxf(C[n][3], 0.f), wb, pr1));
            }
            pr0 += __shfl_xor_sync(0xffffffffu, pr0, 1);
            pr0 += __shfl_xor_sync(0xffffffffu, pr0, 2);
            pr1 += __shfl_xor_sync(0xffffffffu, pr1, 1);
            pr1 += __shfl_xor_sync(0xffffffffu, pr1, 2);
            if (m == 0) {
                if (okr)  out[vr]  = pr0;
                if (okr8) out[vr8] = pr1;
            }
        }
    }

    __syncthreads();
    if (tid < 64)
        atomicAdd(&g_S[tid], colp[0][tid] + colp[1][tid] + colp[2][tid] + colp[3][tid]);
}

// graph-pool scalar + broadcast add
__global__ void add_kernel(const float* __restrict__ W5, float* __restrict__ out) {
    __shared__ float sh[64];
    __shared__ float cval;
    int tid = threadIdx.x;
    if (tid < 64) sh[tid] = fmaxf(g_S[tid], 0.f) * W5[tid];
    __syncthreads();
    if (tid == 0) {
        float s = 0.f;
#pragma unroll
        for (int i = 0; i < 64; i++) s += sh[i];
        cval = s;
    }
    __syncthreads();
    int v = blockIdx.x * blockDim.x + tid;
    if (v < N_NODES) out[v] += cval;
}

// ---------- launch (fork-join: [zero->edge] || [prep], then fused, add) ----------
extern "C" void kernel_launch(void* const* d_in, const int* in_sizes, int n_in,
                              void* d_out, int out_size) {
    const float* mu = (const float*)d_in[0];
    const float* x  = (const float*)d_in[1];
    const int*   ei = (const int*)d_in[2];     // int32 (JAX x64 disabled)
    const float* ew = (const float*)d_in[3];
    const float* W1 = (const float*)d_in[4];
    const float* W2 = (const float*)d_in[5];
    const float* W3 = (const float*)d_in[6];
    const float* W4 = (const float*)d_in[7];
    const float* W5 = (const float*)d_in[8];
    const float* W7 = (const float*)d_in[9];
    float* out = (float*)d_out;

    cudaStream_t s1;
    cudaEvent_t ev0, ev1;
    cudaStreamCreateWithFlags(&s1, cudaStreamNonBlocking);
    cudaEventCreateWithFlags(&ev0, cudaEventDisableTiming);
    cudaEventCreateWithFlags(&ev1, cudaEventDisableTiming);

    cudaEventRecord(ev0, 0);
    cudaStreamWaitEvent(s1, ev0, 0);
    zero_kernel<<<(N_NODES + 255) / 256, 256, 0, s1>>>();
    edge_kernel<<<(NE / 4 + 255) / 256, 256, 0, s1>>>(ei, ew);
    cudaEventRecord(ev1, s1);

    prep_kernel<<<16, 256>>>(W2, W7, W3, W4);

    cudaStreamWaitEvent(0, ev1, 0);
    fused_kernel<<<GRID_F, 128>>>(mu, x, W1, W5, out);
    add_kernel<<<(N_NODES + 255) / 256, 256>>>(W5, out);
}